// round 2
// baseline (speedup 1.0000x reference)
#include <cuda_runtime.h>

typedef unsigned long long u64;

#define B_ 2048
#define I_ 512
#define O_ 256
#define BM 8          // batch rows per tile
#define OT 64         // output cols per tile
#define NTHREADS 64   // 2b x 4o per thread -> 4*16 threads
#define GROUP 8       // i's per prefetch group

__device__ __forceinline__ u64 fma2_(u64 a, u64 b, u64 c) {
    u64 d;
    asm("fma.rn.f32x2 %0, %1, %2, %3;" : "=l"(d) : "l"(a), "l"(b), "l"(c));
    return d;
}
__device__ __forceinline__ u64 mul2_(u64 a, u64 b) {
    u64 d;
    asm("mul.rn.f32x2 %0, %1, %2;" : "=l"(d) : "l"(a), "l"(b));
    return d;
}

__global__ __launch_bounds__(NTHREADS) void l0conj_kernel(
    const float* __restrict__ x,      // [B_, I_]
    const float* __restrict__ w,      // [I_, O_]
    const float* __restrict__ qz,     // [I_]
    float* __restrict__ out)          // [B_, O_]
{
    __shared__ float zs[I_];
    __shared__ float namd[I_ * 2 * BM];   // namd[i*16 + 2b] = namd[i*16+2b+1] = x[b0+b][i]*z[i]-1

    const int tid = threadIdx.x;
    const int bt = blockIdx.x >> 2;        // 256 b-tiles
    const int os = (blockIdx.x & 3) * OT;  // 4 o-slices
    const int b0 = bt * BM;

    // z[i] = clip(sigmoid(qz[i]) * 1.2 - 0.1, 0, 1)
    for (int k = tid; k < I_; k += NTHREADS) {
        float q = qz[k];
        float pi = 1.0f / (1.0f + expf(-q));
        float z = fmaf(pi, 1.2f, -0.1f);
        zs[k] = fminf(fmaxf(z, 0.0f), 1.0f);
    }
    __syncthreads();

    // Stage nam = x*z - 1, duplicated per value so f32x2 dup-pairs come free.
#pragma unroll 4
    for (int k = tid; k < BM * I_; k += NTHREADS) {
        int b = k & (BM - 1);
        int i = k >> 3;
        float v = fmaf(x[(b0 + b) * I_ + i], zs[i], -1.0f);
        int base = i * (2 * BM) + 2 * b;
        namd[base] = v;
        namd[base + 1] = v;
    }
    __syncthreads();

    // Thread tile: 2 consecutive batch rows (2*bg, 2*bg+1) x 4 consecutive o's.
    const int o4 = (tid & 15) * 4;
    const int bg = tid >> 4;                          // 0..3
    const float4* wbase = (const float4*)(w + os + o4);   // wbase[i*64] = w[i][os+o4 .. +3]
    const float* ap = namd + bg * 4;

    const u64 one2 = 0x3F8000003F800000ULL;
    u64 p00 = one2, p01 = one2, p10 = one2, p11 = one2;

    ulonglong2 bufA[GROUP], bufB[GROUP];

#define LOADG(buf, g)                                                        \
    {                                                                        \
        const float4* _p = wbase + (g) * (GROUP * (O_ / 4));                 \
        _Pragma("unroll") for (int u = 0; u < GROUP; ++u)                    \
            (buf)[u] = *(const ulonglong2*)(_p + u * (O_ / 4));              \
    }

#define COMPG(buf)                                                           \
    {                                                                        \
        _Pragma("unroll") for (int u = 0; u < GROUP; ++u) {                  \
            ulonglong2 a = *(const ulonglong2*)ap;                           \
            ap += 2 * BM;                                                    \
            ulonglong2 wv = (buf)[u];                                        \
            p00 = mul2_(p00, fma2_(a.x, wv.x, one2));                        \
            p01 = mul2_(p01, fma2_(a.x, wv.y, one2));                        \
            p10 = mul2_(p10, fma2_(a.y, wv.x, one2));                        \
            p11 = mul2_(p11, fma2_(a.y, wv.y, one2));                        \
        }                                                                    \
    }

    const int NG = I_ / GROUP;  // 64 groups
    LOADG(bufA, 0);
#pragma unroll 1
    for (int it = 0; it < NG / 2; ++it) {
        LOADG(bufB, 2 * it + 1);
        COMPG(bufA);
        LOADG(bufA, (2 * it + 2) & (NG - 1));  // wraps to group 0 on last iter (valid mem)
        COMPG(bufB);
    }

    // Epilogue: p00=(row0 o4,o4+1) p01=(row0 o4+2,o4+3) p10/p11 = row1
    float* op = out + (b0 + bg * 2) * O_ + os + o4;
    *(u64*)(op + 0) = p00;
    *(u64*)(op + 2) = p01;
    *(u64*)(op + O_ + 0) = p10;
    *(u64*)(op + O_ + 2) = p11;
}

extern "C" void kernel_launch(void* const* d_in, const int* in_sizes, int n_in,
                              void* d_out, int out_size) {
    const float* x = nullptr;
    const float* w = nullptr;
    const float* qz = nullptr;
    for (int i = 0; i < n_in; ++i) {
        if (in_sizes[i] == B_ * I_)      x  = (const float*)d_in[i];
        else if (in_sizes[i] == I_ * O_) w  = (const float*)d_in[i];
        else if (in_sizes[i] == I_)      qz = (const float*)d_in[i];
    }
    l0conj_kernel<<<(B_ / BM) * (O_ / OT), NTHREADS>>>(x, w, qz, (float*)d_out);
}

// round 3
// speedup vs baseline: 1.4076x; 1.4076x over previous
#include <cuda_runtime.h>

typedef unsigned long long u64;
typedef unsigned int u32;

#define B_ 2048
#define I_ 512
#define O_ 256
#define NK (I_ / 2)   // 256 i-pairs
#define BM 8          // batch rows per block
#define OT 64         // output cols per block
#define NTH 64        // threads per block
#define RING 16       // w slabs resident (ring)
#define KG 4          // i-pairs per cp.async commit group

// wP[k][o] = (w[2k][o], w[2k+1][o]) packed as f32x2 in a u64.  512KB scratch.
__device__ u64 wP_g[NK * O_];

__device__ __forceinline__ u64 fma2_(u64 a, u64 b, u64 c) {
    u64 d;
    asm("fma.rn.f32x2 %0, %1, %2, %3;" : "=l"(d) : "l"(a), "l"(b), "l"(c));
    return d;
}
__device__ __forceinline__ u64 mul2_(u64 a, u64 b) {
    u64 d;
    asm("mul.rn.f32x2 %0, %1, %2;" : "=l"(d) : "l"(a), "l"(b));
    return d;
}
__device__ __forceinline__ void cpa8(u32 saddr, const void* g) {
    asm volatile("cp.async.ca.shared.global [%0], [%1], 8;" :: "r"(saddr), "l"(g));
}
__device__ __forceinline__ void cpa_commit() {
    asm volatile("cp.async.commit_group;");
}
__device__ __forceinline__ void cpa_wait3() {
    asm volatile("cp.async.wait_group 3;");
}

// ---------------- K1: pack w into i-pair lanes ----------------
__global__ void pack_w_kernel(const float* __restrict__ w) {
    int k = blockIdx.x;   // 0..NK-1
    int o = threadIdx.x;  // 0..O_-1
    float lo = w[(2 * k) * O_ + o];
    float hi = w[(2 * k + 1) * O_ + o];
    u64 v;
    asm("mov.b64 %0, {%1, %2};" : "=l"(v) : "f"(lo), "f"(hi));
    wP_g[k * O_ + o] = v;
}

// ---------------- K2: main ----------------
__global__ __launch_bounds__(NTH, 8) void l0conj_main(
    const float* __restrict__ x,      // [B_, I_]
    const float* __restrict__ qz,     // [I_]
    float* __restrict__ out)          // [B_, O_]
{
    __shared__ __align__(16) float zs[I_];            // 2KB
    __shared__ __align__(16) u64 aP[NK * BM];         // 16KB  aP[k*8+r] = (a[r][2k], a[r][2k+1])
    __shared__ __align__(16) u64 wring[RING * OT];    // 8KB

    const int tid = threadIdx.x;
    const int bt = blockIdx.x >> 2;
    const int os = (blockIdx.x & 3) * OT;
    const int b0 = bt * BM;

    const u32 wsm = (u32)__cvta_generic_to_shared(wring);

    // Kick off the first RING w-slabs immediately (overlaps z/a precompute).
    // Slab ks lives at ring slot ks & (RING-1); thread t copies one u64.
#pragma unroll
    for (int g = 0; g < RING / KG; ++g) {
#pragma unroll
        for (int u = 0; u < KG; ++u) {
            int ks = g * KG + u;
            cpa8(wsm + (u32)((ks * OT + tid) * 8), wP_g + ks * O_ + os + tid);
        }
        cpa_commit();
    }

    // z[i] = clip(sigmoid(qz[i]) * 1.2 - 0.1, 0, 1)
    for (int i = tid; i < I_; i += NTH) {
        float q = qz[i];
        float pi = 1.0f / (1.0f + expf(-q));
        zs[i] = fminf(fmaxf(fmaf(pi, 1.2f, -0.1f), 0.0f), 1.0f);
    }
    __syncthreads();

    const u64 one2 = 0x3F8000003F800000ULL;   // ( 1, 1)
    const u64 neg2 = 0xBF800000BF800000ULL;   // (-1,-1)
    const u64* zd = (const u64*)zs;           // zd[k] = (z[2k], z[2k+1])

    // a precompute: a = x*z - 1 as natural i-pair lanes. Coalesced x reads.
#pragma unroll
    for (int j = 0; j < NK / NTH; ++j) {
        int k = tid + NTH * j;
        u64 zk = zd[k];
#pragma unroll
        for (int r = 0; r < BM; ++r) {
            u64 x2 = *(const u64*)(x + (b0 + r) * I_ + 2 * k);
            aP[k * BM + r] = fma2_(x2, zk, neg2);
        }
    }
    __syncthreads();

    // Thread tile: 2 batch rows (2bg, 2bg+1) x 4 o's (og*4..+3). Lanes = (i even, i odd).
    const int bg = tid & 3;
    const int og = tid >> 2;

    u64 p[2][4];
#pragma unroll
    for (int r = 0; r < 2; ++r)
#pragma unroll
        for (int c = 0; c < 4; ++c) p[r][c] = one2;

    const u64* aBase = aP + 2 * bg;           // + k*BM
    const u64* wBase = wring + og * 4;        // + (k & 15)*OT

    int kpref = RING;
#pragma unroll 1
    for (int kb = 0; kb < NK; kb += KG) {
        cpa_wait3();           // slabs kb..kb+3 ready (invariant: 3 groups in flight)
        __syncwarp();

        const u64* wSlot = wBase + (kb & (RING - 1)) * OT;
        const u64* aSlot = aBase + kb * BM;
#pragma unroll
        for (int u = 0; u < KG; ++u) {
            ulonglong2 a2 = *(const ulonglong2*)(aSlot + u * BM);       // rows 2bg,2bg+1
            ulonglong2 w01 = *(const ulonglong2*)(wSlot + u * OT);      // o4, o4+1
            ulonglong2 w23 = *(const ulonglong2*)(wSlot + u * OT + 2);  // o4+2, o4+3
            p[0][0] = mul2_(p[0][0], fma2_(a2.x, w01.x, one2));
            p[0][1] = mul2_(p[0][1], fma2_(a2.x, w01.y, one2));
            p[0][2] = mul2_(p[0][2], fma2_(a2.x, w23.x, one2));
            p[0][3] = mul2_(p[0][3], fma2_(a2.x, w23.y, one2));
            p[1][0] = mul2_(p[1][0], fma2_(a2.y, w01.x, one2));
            p[1][1] = mul2_(p[1][1], fma2_(a2.y, w01.y, one2));
            p[1][2] = mul2_(p[1][2], fma2_(a2.y, w23.x, one2));
            p[1][3] = mul2_(p[1][3], fma2_(a2.y, w23.y, one2));
        }

        // Commit next group every iteration (tail wraps; redundant fetch is harmless
        // and keeps the wait_group-3 invariant exact).
#pragma unroll
        for (int u = 0; u < KG; ++u) {
            int ks = kpref + u;
            int slot = ks & (RING - 1);
            int ksrc = ks & (NK - 1);
            cpa8(wsm + (u32)((slot * OT + tid) * 8), wP_g + ksrc * O_ + os + tid);
        }
        cpa_commit();
        kpref += KG;
    }

    // Epilogue: scalar result = lane0 * lane1 (even-i product * odd-i product).
#pragma unroll
    for (int r = 0; r < 2; ++r) {
        float4 v;
        float lo, hi;
        asm("mov.b64 {%0, %1}, %2;" : "=f"(lo), "=f"(hi) : "l"(p[r][0])); v.x = lo * hi;
        asm("mov.b64 {%0, %1}, %2;" : "=f"(lo), "=f"(hi) : "l"(p[r][1])); v.y = lo * hi;
        asm("mov.b64 {%0, %1}, %2;" : "=f"(lo), "=f"(hi) : "l"(p[r][2])); v.z = lo * hi;
        asm("mov.b64 {%0, %1}, %2;" : "=f"(lo), "=f"(hi) : "l"(p[r][3])); v.w = lo * hi;
        *(float4*)(out + (b0 + 2 * bg + r) * O_ + os + og * 4) = v;
    }
}

extern "C" void kernel_launch(void* const* d_in, const int* in_sizes, int n_in,
                              void* d_out, int out_size) {
    const float* x = nullptr;
    const float* w = nullptr;
    const float* qz = nullptr;
    for (int i = 0; i < n_in; ++i) {
        if (in_sizes[i] == B_ * I_)      x  = (const float*)d_in[i];
        else if (in_sizes[i] == I_ * O_) w  = (const float*)d_in[i];
        else if (in_sizes[i] == I_)      qz = (const float*)d_in[i];
    }
    pack_w_kernel<<<NK, O_>>>(w);
    l0conj_main<<<(B_ / BM) * (O_ / OT), NTH>>>(x, qz, (float*)d_out);
}